// round 8
// baseline (speedup 1.0000x reference)
#include <cuda_runtime.h>
#include <cstdint>
#include <cfloat>
#include <math.h>

#define VOC   10000
#define EMB   512
#define HID   1024
#define BATCH 128
#define SEQT  64
#define STEPS 63
#define CTXW  4096
#define G4H   4096
#define NBLK  128
#define NTHR  512
#define NTILE_C 313
#define KC    8

typedef long long ll;

// ---------------- persistent device scratch ----------------------------------
__device__ __align__(128) float g_hn[BATCH * G4H];
__device__ __align__(128) float g_x[BATCH * EMB];
__device__ __align__(128) float g_h1[2][BATCH * HID];
__device__ __align__(128) float g_h2[2][BATCH * HID];
__device__ __align__(128) float g_pmax[BATCH][NTILE_C];
__device__ __align__(128) int   g_pidx[BATCH][NTILE_C];
__device__ int   g_ctrC[STEPS];
__device__ int   g_myTile[NBLK];
__device__ int   g_selTok[NBLK];
__device__ float g_selSc[NBLK];
__device__ unsigned g_count;
__device__ unsigned g_gen;

__device__ __forceinline__ float sigmf(float x) { return 1.0f / (1.0f + expf(-x)); }

__device__ __forceinline__ void ffma2(ll& d, ll a, ll b) {
    asm("fma.rn.f32x2 %0, %1, %2, %0;" : "+l"(d) : "l"(a), "l"(b));
}
__device__ __forceinline__ void addf2(ll& d, ll b) {
    asm("add.rn.f32x2 %0, %0, %1;" : "+l"(d) : "l"(b));
}
__device__ __forceinline__ ll packf2(float lo, float hi) {
    ll r; asm("mov.b64 %0, {%1, %2};" : "=l"(r) : "f"(lo), "f"(hi)); return r;
}
__device__ __forceinline__ float2 unpackf2(ll v) {
    float2 f; asm("mov.b64 {%0, %1}, %2;" : "=f"(f.x), "=f"(f.y) : "l"(v)); return f;
}

// ---------------- grid-wide sense barrier ------------------------------------
__device__ __forceinline__ void gbar() {
    __syncthreads();
    if (threadIdx.x == 0) {
        __threadfence();
        unsigned gen = *((volatile unsigned*)&g_gen);
        unsigned arrived = atomicAdd(&g_count, 1);
        if (arrived == NBLK - 1) {
            atomicExch(&g_count, 0);
            __threadfence();
            atomicAdd(&g_gen, 1);
        } else {
            while (*((volatile unsigned*)&g_gen) == gen) __nanosleep(64);
        }
        __threadfence();
    }
    __syncthreads();
}

// ---------------- FFMA2 GEMM engine ------------------------------------------
// C[128 x 32] += A[128 x K] * W^T.
// 16 warps = (ks 0..3 k-slice) x (cs 0..3 col-slice of 8 cols).
// Lane: rg = lane>>1 (rowpair base), cg = lane&1 (4-col half).
// Thread tile: rowpairs {rg+16i, i<4} x cols {cs*8+cg*4+j, j<4}; acc[i][j] =
// {C[2rp][c], C[2rp+1][c]} packed f32x2.
// A smem: per-ks double-buffered [k][row] (stride 128) -> av natural LDS.64.
// W smem: warp-private double-buffered dup pairs [k][8] ll -> wv LDS.64 {w,w}.
// One __syncthreads per KC-chunk.
template<bool GATED>
__device__ __forceinline__ void gemm_run(ll (&acc)[4][4],
    const float* __restrict__ A, int lda,
    const float* __restrict__ W, int ldw, int wcol0,
    int colBase, int growMax, int kLen, float* __restrict__ sMem)
{
    const int tid  = threadIdx.x;
    const int ks   = tid >> 7;
    const int gtid = tid & 127;
    const int wid  = tid >> 5;
    const int cs   = wid & 3;
    const int lane = tid & 31;
    const int rg   = lane >> 1;
    const int cg   = lane & 1;

    float* const sA = sMem + ks * 2048;              // [2][8][128]
    ll*    const sW = (ll*)(sMem + 8192) + wid * 128; // [2][8][8]

    const int wcol8 = lane >> 2;           // 0..7
    const int kq    = (lane & 3) * 2;      // 0,2,4,6
    int grow;
    if (GATED) grow = cs * HID + colBase + wcol8;
    else { grow = colBase + cs * 8 + wcol8; if (grow > growMax) grow = growMax; }
    const int kBeg = ks * kLen;
    const float* ap = A + (size_t)gtid * lda + kBeg;
    const float* wp = W + (size_t)grow * ldw + wcol0 + kBeg + kq;

    float4 pa0 = __ldcg((const float4*)ap);
    float4 pa1 = __ldcg((const float4*)(ap + 4));
    float2 pw  = __ldcg((const float2*)wp);

    const int nch = kLen / KC;
    for (int c = 0; c < nch; c++) {
        float* a = sA + (c & 1) * 1024;
        ll*    w = sW + (c & 1) * 64;
        a[0*128 + gtid] = pa0.x; a[1*128 + gtid] = pa0.y;
        a[2*128 + gtid] = pa0.z; a[3*128 + gtid] = pa0.w;
        a[4*128 + gtid] = pa1.x; a[5*128 + gtid] = pa1.y;
        a[6*128 + gtid] = pa1.z; a[7*128 + gtid] = pa1.w;
        w[kq * 8 + wcol8]       = packf2(pw.x, pw.x);
        w[(kq + 1) * 8 + wcol8] = packf2(pw.y, pw.y);
        if (c + 1 < nch) {
            int off = (c + 1) * KC;
            pa0 = __ldcg((const float4*)(ap + off));
            pa1 = __ldcg((const float4*)(ap + off + 4));
            pw  = __ldcg((const float2*)(wp + off));
        }
        __syncthreads();
        #pragma unroll
        for (int kk = 0; kk < KC; kk++) {
            ll wv0 = w[kk * 8 + cg * 4 + 0];
            ll wv1 = w[kk * 8 + cg * 4 + 1];
            ll wv2 = w[kk * 8 + cg * 4 + 2];
            ll wv3 = w[kk * 8 + cg * 4 + 3];
            #pragma unroll
            for (int i = 0; i < 4; i++) {
                ll av = *(const ll*)(a + kk * 128 + 2 * (rg + 16 * i));
                ffma2(acc[i][0], av, wv0);
                ffma2(acc[i][1], av, wv1);
                ffma2(acc[i][2], av, wv2);
                ffma2(acc[i][3], av, wv3);
            }
        }
    }
}

// Cross-ks reduction: warps ks1..3 dump (interleaved, conflict-free), ks0 sums.
__device__ __forceinline__ void reduce_ks(ll (&acc)[4][4], float* sMem) {
    const int tid  = threadIdx.x;
    const int wid  = tid >> 5;
    const int lane = tid & 31;
    ll* red = (ll*)sMem;   // [16 regs][384 slots]
    __syncthreads();
    if (wid >= 4) {
        int slot = (wid - 4) * 32 + lane;
        #pragma unroll
        for (int i = 0; i < 4; i++)
            #pragma unroll
            for (int j = 0; j < 4; j++)
                red[(i * 4 + j) * 384 + slot] = acc[i][j];
    }
    __syncthreads();
    if (wid < 4) {
        #pragma unroll
        for (int s = 0; s < 3; s++) {
            int slot = (s * 4 + wid) * 32 + lane;
            #pragma unroll
            for (int i = 0; i < 4; i++)
                #pragma unroll
                for (int j = 0; j < 4; j++)
                    addf2(acc[i][j], red[(i * 4 + j) * 384 + slot]);
        }
    }
    __syncthreads();
}

__global__ void __launch_bounds__(NTHR, 1) lstm_kernel(
    const float* __restrict__ h_n,   const int* __restrict__ expanded,
    const int* __restrict__ tfmask,  const float* __restrict__ dropm,
    const float* __restrict__ embW,
    const float* __restrict__ Wih1,  const float* __restrict__ Whh1,
    const float* __restrict__ bih1,  const float* __restrict__ bhh1,
    const float* __restrict__ Wih2,  const float* __restrict__ Whh2,
    const float* __restrict__ bih2,  const float* __restrict__ bhh2,
    const float* __restrict__ Wout,  const float* __restrict__ bout,
    float* __restrict__ out)
{
    __shared__ __align__(16) float sMem[12288];   // exactly 48 KB, aliased

    const int tid  = threadIdx.x;
    const int blk  = blockIdx.x;
    const int j0   = blk * 8;
    const int ks   = tid >> 7;
    const int wid  = tid >> 5;
    const int cs   = wid & 3;
    const int lane = tid & 31;
    const int rg   = lane >> 1;
    const int cg   = lane & 1;

    // ---------------- init ----------------
    for (int i = blk * NTHR + tid; i < BATCH * HID; i += NBLK * NTHR) {
        g_h1[0][i] = 0.f; g_h2[0][i] = 0.f;
    }
    for (int i = blk * NTHR + tid; i < BATCH * EMB; i += NBLK * NTHR) {
        int b = i / EMB; int e = i - b * EMB;
        int tok = expanded[b * SEQT];
        g_x[i] = dropm[tok] * embW[(size_t)tok * EMB + e];
    }
    if (blk == 0) {
        for (int i = tid; i < STEPS; i += NTHR) g_ctrC[i] = 0;
    }
    {   // g_hn = h_n @ Wih1[:, E:].T + bih1 + bhh1 (this block's gate tile)
        ll acc[4][4];
        #pragma unroll
        for (int i = 0; i < 4; i++)
            #pragma unroll
            for (int j = 0; j < 4; j++) acc[i][j] = packf2(0.f, 0.f);
        gemm_run<true>(acc, h_n, CTXW, Wih1, EMB + CTXW, EMB, j0, 0, 1024, sMem);
        reduce_ks(acc, sMem);
        if (wid < 4) {
            #pragma unroll
            for (int i = 0; i < 4; i++) {
                int r0 = 2 * (rg + 16 * i);
                #pragma unroll
                for (int j = 0; j < 4; j++) {
                    int base = cs * HID + j0 + cg * 4 + j;
                    float2 v = unpackf2(acc[i][j]);
                    float bb = bih1[base] + bhh1[base];
                    g_hn[(size_t)r0 * G4H + base]       = v.x + bb;
                    g_hn[(size_t)(r0 + 1) * G4H + base] = v.y + bb;
                }
            }
        }
    }
    gbar();

    float c1s[2] = {0.f, 0.f};
    float c2s[2] = {0.f, 0.f};

    for (int t = 0; t < STEPS; t++) {
        const float* h1o = g_h1[t & 1];
        float*       h1n = g_h1[(t + 1) & 1];
        const float* h2o = g_h2[t & 1];
        float*       h2n = g_h2[(t + 1) & 1];

        // ---------- phase A: layer-1 gates + cell ----------
        {
            ll acc[4][4];
            #pragma unroll
            for (int i = 0; i < 4; i++) {
                if (i == ks) {   // distribute hn preload across ks groups
                    int r0 = 2 * (rg + 16 * i);
                    #pragma unroll
                    for (int j = 0; j < 4; j++) {
                        int base = cs * HID + j0 + cg * 4 + j;
                        acc[i][j] = packf2(__ldcg(&g_hn[(size_t)r0 * G4H + base]),
                                           __ldcg(&g_hn[(size_t)(r0 + 1) * G4H + base]));
                    }
                } else {
                    #pragma unroll
                    for (int j = 0; j < 4; j++) acc[i][j] = packf2(0.f, 0.f);
                }
            }
            gemm_run<true>(acc, g_x, EMB, Wih1, EMB + CTXW, 0, j0, 0, 128, sMem);
            gemm_run<true>(acc, h1o, HID, Whh1, HID, 0, j0, 0, 256, sMem);
            reduce_ks(acc, sMem);
            float* sGf = sMem;   // [128][33]
            if (wid < 4) {
                #pragma unroll
                for (int i = 0; i < 4; i++) {
                    int r0 = 2 * (rg + 16 * i);
                    #pragma unroll
                    for (int j = 0; j < 4; j++) {
                        int c = cs * 8 + cg * 4 + j;
                        float2 v = unpackf2(acc[i][j]);
                        sGf[r0 * 33 + c]       = v.x;
                        sGf[(r0 + 1) * 33 + c] = v.y;
                    }
                }
            }
            __syncthreads();
            #pragma unroll
            for (int jj = 0; jj < 2; jj++) {
                int p = tid + jj * NTHR;
                int r = p >> 3, jl = p & 7;
                float ii = sGf[r * 33 +      jl];
                float ff = sGf[r * 33 +  8 + jl];
                float gg = sGf[r * 33 + 16 + jl];
                float oo = sGf[r * 33 + 24 + jl];
                float cn = sigmf(ff) * c1s[jj] + sigmf(ii) * tanhf(gg);
                c1s[jj] = cn;
                h1n[r * HID + j0 + jl] = sigmf(oo) * tanhf(cn);
            }
        }
        gbar();

        // ---------- phase B: layer-2 gates + cell ----------
        {
            ll acc[4][4];
            if (wid < 4) {
                #pragma unroll
                for (int j = 0; j < 4; j++) {
                    int base = cs * HID + j0 + cg * 4 + j;
                    float bb = bih2[base] + bhh2[base];
                    #pragma unroll
                    for (int i = 0; i < 4; i++) acc[i][j] = packf2(bb, bb);
                }
            } else {
                #pragma unroll
                for (int i = 0; i < 4; i++)
                    #pragma unroll
                    for (int j = 0; j < 4; j++) acc[i][j] = packf2(0.f, 0.f);
            }
            gemm_run<true>(acc, h1n, HID, Wih2, HID, 0, j0, 0, 256, sMem);
            gemm_run<true>(acc, h2o, HID, Whh2, HID, 0, j0, 0, 256, sMem);
            reduce_ks(acc, sMem);
            float* sGf = sMem;
            if (wid < 4) {
                #pragma unroll
                for (int i = 0; i < 4; i++) {
                    int r0 = 2 * (rg + 16 * i);
                    #pragma unroll
                    for (int j = 0; j < 4; j++) {
                        int c = cs * 8 + cg * 4 + j;
                        float2 v = unpackf2(acc[i][j]);
                        sGf[r0 * 33 + c]       = v.x;
                        sGf[(r0 + 1) * 33 + c] = v.y;
                    }
                }
            }
            __syncthreads();
            #pragma unroll
            for (int jj = 0; jj < 2; jj++) {
                int p = tid + jj * NTHR;
                int r = p >> 3, jl = p & 7;
                float ii = sGf[r * 33 +      jl];
                float ff = sGf[r * 33 +  8 + jl];
                float gg = sGf[r * 33 + 16 + jl];
                float oo = sGf[r * 33 + 24 + jl];
                float cn = sigmf(ff) * c2s[jj] + sigmf(ii) * tanhf(gg);
                c2s[jj] = cn;
                h2n[r * HID + j0 + jl] = sigmf(oo) * tanhf(cn);
            }
        }
        gbar();

        // ---------- phase C: logits GEMM + argmax partials (work stealing) ----
        for (;;) {
            __syncthreads();
            if (tid == 0) g_myTile[blk] = atomicAdd(&g_ctrC[t], 1);
            __syncthreads();
            int tile = g_myTile[blk];
            if (tile >= NTILE_C) break;
            int n0 = tile * 32;
            ll acc[4][4];
            if (wid < 4) {
                #pragma unroll
                for (int j = 0; j < 4; j++) {
                    int col = n0 + cs * 8 + cg * 4 + j;
                    float bb = (col < VOC) ? bout[col] : 0.f;
                    #pragma unroll
                    for (int i = 0; i < 4; i++) acc[i][j] = packf2(bb, bb);
                }
            } else {
                #pragma unroll
                for (int i = 0; i < 4; i++)
                    #pragma unroll
                    for (int j = 0; j < 4; j++) acc[i][j] = packf2(0.f, 0.f);
            }
            gemm_run<false>(acc, h2n, HID, Wout, HID, 0, n0, VOC - 1, 256, sMem);
            reduce_ks(acc, sMem);
            float* sMxV = sMem;              // [128][4]
            int*   sMxI = (int*)(sMem + 512);
            if (wid < 4) {
                bool full = (n0 + 32 <= VOC);
                #pragma unroll
                for (int i = 0; i < 4; i++) {
                    float2 v[4];
                    #pragma unroll
                    for (int j = 0; j < 4; j++) v[j] = unpackf2(acc[i][j]);
                    #pragma unroll
                    for (int e = 0; e < 2; e++) {
                        int r = 2 * (rg + 16 * i) + e;
                        int cbase = n0 + cs * 8 + cg * 4;
                        size_t ob = ((size_t)t * BATCH + r) * VOC + cbase;
                        float vv[4];
                        #pragma unroll
                        for (int j = 0; j < 4; j++) vv[j] = e ? v[j].y : v[j].x;
                        float bv = -FLT_MAX; int bc = 0x7fffffff;
                        if (full) {
                            __stcs((float4*)(out + ob),
                                   make_float4(vv[0], vv[1], vv[2], vv[3]));
                            #pragma unroll
                            for (int q = 0; q < 4; q++)
                                if (vv[q] > bv) { bv = vv[q]; bc = cbase + q; }
                        } else {
                            #pragma unroll
                            for (int q = 0; q < 4; q++) {
                                int col = cbase + q;
                                if (col < VOC) {
                                    __stcs(out + ob + q, vv[q]);
                                    if (vv[q] > bv) { bv = vv[q]; bc = col; }
                                }
                            }
                        }
                        // combine the two 4-col halves (cg pair)
                        float ov = __shfl_xor_sync(0xffffffffu, bv, 1);
                        int   oc = __shfl_xor_sync(0xffffffffu, bc, 1);
                        if (ov > bv || (ov == bv && oc < bc)) { bv = ov; bc = oc; }
                        if (cg == 0) { sMxV[r * 4 + cs] = bv; sMxI[r * 4 + cs] = bc; }
                    }
                }
            }
            __syncthreads();
            if (wid == 0) {
                #pragma unroll
                for (int q = 0; q < 4; q++) {
                    int r = lane + 32 * q;
                    float bv = sMxV[r * 4]; int bc = sMxI[r * 4];
                    #pragma unroll
                    for (int s = 1; s < 4; s++) {
                        float v = sMxV[r * 4 + s]; int c2 = sMxI[r * 4 + s];
                        if (v > bv || (v == bv && c2 < bc)) { bv = v; bc = c2; }
                    }
                    g_pmax[r][tile] = bv; g_pidx[r][tile] = bc;
                }
            }
        }
        gbar();

        // ---------- phase D: final argmax + next-input select ----------
        {
            float* s_rv = sMem;
            int*   s_ri = (int*)(sMem + NTHR);
            int b = blk;
            float bv = -FLT_MAX; int bc = 0x7fffffff;
            if (tid < NTILE_C) {
                bv = __ldcg(&g_pmax[b][tid]);
                bc = __ldcg(&g_pidx[b][tid]);
            }
            s_rv[tid] = bv; s_ri[tid] = bc;
            __syncthreads();
            for (int s = NTHR / 2; s > 0; s >>= 1) {
                if (tid < s) {
                    float v = s_rv[tid + s]; int c2 = s_ri[tid + s];
                    if (v > s_rv[tid] || (v == s_rv[tid] && c2 < s_ri[tid])) {
                        s_rv[tid] = v; s_ri[tid] = c2;
                    }
                }
                __syncthreads();
            }
            if (tid == 0) {
                int m = tfmask[t * BATCH + b];
                int tok; float sc;
                if (m == 1) { tok = s_ri[0]; sc = 1.0f; }
                else        { tok = expanded[b * SEQT + t + 1]; sc = dropm[tok]; }
                g_selTok[blk] = tok; g_selSc[blk] = sc;
            }
            __syncthreads();
            int tok = g_selTok[blk]; float sc = g_selSc[blk];
            g_x[b * EMB + tid] = sc * embW[(size_t)tok * EMB + tid];
        }
        gbar();
    }
}

extern "C" void kernel_launch(void* const* d_in, const int* in_sizes, int n_in,
                              void* d_out, int out_size) {
    (void)in_sizes; (void)n_in; (void)out_size;
    lstm_kernel<<<NBLK, NTHR>>>(
        (const float*)d_in[0],  (const int*)d_in[1],  (const int*)d_in[2],
        (const float*)d_in[3],  (const float*)d_in[4], (const float*)d_in[5],
        (const float*)d_in[6],  (const float*)d_in[7], (const float*)d_in[8],
        (const float*)d_in[9],  (const float*)d_in[10], (const float*)d_in[11],
        (const float*)d_in[12], (const float*)d_in[13], (const float*)d_in[14],
        (float*)d_out);
}